// round 12
// baseline (speedup 1.0000x reference)
#include <cuda_runtime.h>
#include <cuda_fp16.h>
#include <cstdint>

#define NTHREADS 256
#define NBLOCKS  444            // 3 CTAs/SM x 148 SMs

// ---------------- PTX helpers ----------------
__device__ __forceinline__ uint32_t smem_u32(const void* p) {
    uint32_t a;
    asm("{ .reg .u64 t; cvta.to.shared.u64 t, %1; cvt.u32.u64 %0, t; }" : "=r"(a) : "l"(p));
    return a;
}
__device__ __forceinline__ void ldmx2(uint32_t& r0, uint32_t& r1, uint32_t addr) {
    asm volatile("ldmatrix.sync.aligned.m8n8.x2.shared.b16 {%0,%1}, [%2];"
                 : "=r"(r0), "=r"(r1) : "r"(addr));
}
__device__ __forceinline__ void ldmx4(uint32_t& r0, uint32_t& r1, uint32_t& r2, uint32_t& r3,
                                      uint32_t addr) {
    asm volatile("ldmatrix.sync.aligned.m8n8.x4.shared.b16 {%0,%1,%2,%3}, [%4];"
                 : "=r"(r0), "=r"(r1), "=r"(r2), "=r"(r3) : "r"(addr));
}
__device__ __forceinline__ void mma_k8_f16(uint32_t& d0, uint32_t& d1,
                                           uint32_t a0, uint32_t a1, uint32_t b0,
                                           uint32_t zero) {
    asm volatile("mma.sync.aligned.m16n8k8.row.col.f16.f16.f16.f16 "
                 "{%0,%1}, {%2,%3}, {%4}, {%5,%5};"
                 : "=r"(d0), "=r"(d1)
                 : "r"(a0), "r"(a1), "r"(b0), "r"(zero));
}
__device__ __forceinline__ void mma_k16_f16(uint32_t& d0, uint32_t& d1,
                                            uint32_t a0, uint32_t a1, uint32_t a2,
                                            uint32_t a3, uint32_t b0, uint32_t b1) {
    asm volatile("mma.sync.aligned.m16n8k16.row.col.f16.f16.f16.f16 "
                 "{%0,%1}, {%2,%3,%4,%5}, {%6,%7}, {%0,%1};"
                 : "+r"(d0), "+r"(d1)
                 : "r"(a0), "r"(a1), "r"(a2), "r"(a3), "r"(b0), "r"(b1));
}
__device__ __forceinline__ void mma_k16(float* d, uint32_t a0, uint32_t a1, uint32_t a2,
                                        uint32_t a3, uint32_t b0, uint32_t b1) {
    asm volatile("mma.sync.aligned.m16n8k16.row.col.f32.f16.f16.f32 "
                 "{%0,%1,%2,%3}, {%4,%5,%6,%7}, {%8,%9}, {%0,%1,%2,%3};"
                 : "+f"(d[0]), "+f"(d[1]), "+f"(d[2]), "+f"(d[3])
                 : "r"(a0), "r"(a1), "r"(a2), "r"(a3), "r"(b0), "r"(b1));
}
__device__ __forceinline__ uint32_t pack_h2(float x, float y) {
    __half2 h = __floats2half2_rn(x, y);          // low half = x
    return *reinterpret_cast<uint32_t*>(&h);
}
__device__ __forceinline__ uint32_t relu_h2(uint32_t u) {
    __half2 h = *reinterpret_cast<__half2*>(&u);
    __half2 z = __floats2half2_rn(0.f, 0.f);
    __half2 r = __hmax2(h, z);
    return *reinterpret_cast<uint32_t*>(&r);
}

// ---------------- shared memory (dynamic, ~50 KB -> 3 CTAs/SM) ----------------
struct SmemT {
    __align__(16) uint8_t  w2t[128 * 256];     // W2^T [n][k] half, swizzled (32 KB)
    __align__(16) __half   w1t[128 * 8];       // W1^T (+b1 in k7)            (2 KB)
    __align__(16) __half   inv[2][64 * 8];     // invariants, double-buffered (2 KB)
    __align__(16) float    scal[2][64 * 8];    // {a,b,c,d,r00,r01}, dbl-buf  (4 KB)
    __align__(16) __half   w3th[4 * 128];      // W3eff^T [nn][k] (3 rows+0)  (1 KB)
    __align__(16) float    part[2][4 * 64 * 4];// layer-3 partials, dbl-buf   (8 KB)
    __align__(16) uint32_t b2u[64];            // b2 packed half2 per n-pair
    float b3e[4];                              // {b3_0, (b3_1+b3_2)/2, b3_3, 0}
};

__device__ __forceinline__ void compute_inv(SmemT* sm, int p, int row, float4 f) {
    const float a = f.x, b = f.y, c = f.z, d = f.w;
    const float t0 = a + d, t1 = b - c, t2 = a - d, t3 = b + c;
    const float pp = sqrtf(t0*t0 + t1*t1);
    const float qq = sqrtf(t2*t2 + t3*t3);
    const float i0 = 0.5f*(pp + qq) - 1.f;
    const float i1 = 0.5f*fabsf(pp - qq) - 1.f;
    const float i2 = a*a + c*c - 1.f;
    const float i3 = a*b + c*d;          // == i4
    const float i5 = b*b + d*d - 1.f;
    const float i6 = a*d - b*c - 1.f;
    const float rp  = 1.f / pp;
    const float r00 = t0 * rp, r01 = t1 * rp;

    uint4 u;
    u.x = pack_h2(i0, i1);
    u.y = pack_h2(i2, i3);
    u.z = pack_h2(i3, i5);
    u.w = pack_h2(i6, 1.0f);             // k7 = 1.0 (bias input)
    reinterpret_cast<uint4*>(sm->inv[p])[row] = u;

    float4* s = reinterpret_cast<float4*>(sm->scal[p] + row * 8);
    s[0] = f;
    s[1] = make_float4(r00, r01, 0.f, 0.f);
}

__global__ __launch_bounds__(NTHREADS, 3)
void defcorr_mma(const float* __restrict__ Fg,
                 const float* __restrict__ W1, const float* __restrict__ b1,
                 const float* __restrict__ W2, const float* __restrict__ b2,
                 const float* __restrict__ W3, const float* __restrict__ b3,
                 float* __restrict__ out, int n)
{
    extern __shared__ char dsm[];
    SmemT* sm = reinterpret_cast<SmemT*>(dsm);

    const int tid  = threadIdx.x;
    const int lane = tid & 31;
    const int warp = tid >> 5;
    const int rg   = warp >> 2;               // row group (0..1): 32 rows each
    const int cq   = warp & 3;                // column quarter: 32 cols each
    const int warpm0 = rg * 32;

    // ---------- stage weights (once) ----------
    for (int i = tid; i < 128 * 128; i += NTHREADS) {
        const int nn = i >> 7, k = i & 127;
        const int c  = k >> 3;
        const int cs = (c & 8) | ((c ^ nn) & 7);
        const uint32_t off = (uint32_t)nn * 256u + (uint32_t)cs * 16u + (uint32_t)(k & 7) * 2u;
        *reinterpret_cast<__half*>(sm->w2t + off) = __float2half(W2[k * 128 + nn]);
    }
    for (int i = tid; i < 128 * 8; i += NTHREADS) {
        const int nn = i >> 3, k = i & 7;
        sm->w1t[i] = __float2half(k < 7 ? W1[k * 128 + nn] : b1[nn]);
    }
    for (int i = tid; i < 4 * 128; i += NTHREADS) {
        const int nn = i >> 7, k = i & 127;
        float v = 0.f;
        if (nn == 0) v = W3[k * 4 + 0];
        else if (nn == 1) v = 0.5f * (W3[k * 4 + 1] + W3[k * 4 + 2]);   // folded symmetrize
        else if (nn == 2) v = W3[k * 4 + 3];
        sm->w3th[i] = __float2half(v);
    }
    for (int i = tid; i < 64; i += NTHREADS)
        sm->b2u[i] = pack_h2(b2[2*i], b2[2*i + 1]);
    if (tid == 0) {
        sm->b3e[0] = b3[0];
        sm->b3e[1] = 0.5f * (b3[1] + b3[2]);
        sm->b3e[2] = b3[3];
        sm->b3e[3] = 0.f;
    }

    const uint32_t uW2  = smem_u32(sm->w2t);
    const uint32_t uW1  = smem_u32(sm->w1t);
    const uint32_t uInv = smem_u32(sm->inv[0]);

    const int rowPart = ((lane >> 4) << 3) | (lane & 7);
    const int kSel    = (lane >> 3) & 1;
    const uint32_t bAddrBase  = uW2 + (uint32_t)rowPart * 256u + (uint32_t)(cq * 2) * 4096u;
    const uint32_t w1AddrBase = uW1 + (uint32_t)(lane & 15) * 16u;

    __syncthreads();   // weights staged

    const int ntiles = (n + 63) >> 6;         // 64-row tiles

    // ---------- prologue: invariants for first tile into buffer 0 ----------
    if (tid < 64 && blockIdx.x < ntiles) {
        const int elem = blockIdx.x * 64 + tid;
        float4 f = make_float4(1.f, 0.f, 0.f, 1.f);
        if (elem < n) f = reinterpret_cast<const float4*>(Fg)[elem];
        compute_inv(sm, 0, tid, f);
    }
    __syncthreads();

    const uint32_t zero = 0u;
    int p = 0;
    for (int tile = blockIdx.x; tile < ntiles; tile += gridDim.x) {
        const int ntile = tile + gridDim.x;

        // ---------- prefetch next tile's F early (hides LDG behind MMA) ----------
        float4 fnx = make_float4(1.f, 0.f, 0.f, 1.f);
        if (tid < 64 && ntile < ntiles) {
            const int e = ntile * 64 + tid;
            if (e < n) fnx = reinterpret_cast<const float4*>(Fg)[e];
        }

        // ---------- A-inputs for layer 1 (reads inv[p]) ----------
        const uint32_t uInvP = uInv + (uint32_t)p * 1024u;
        uint32_t ai[2][2];
        ldmx2(ai[0][0], ai[0][1], uInvP + (uint32_t)(warpm0      + (lane & 15)) * 16u);
        ldmx2(ai[1][0], ai[1][1], uInvP + (uint32_t)(warpm0 + 16 + (lane & 15)) * 16u);

        // ---------- init layer-2 f16 accumulators with b2 ----------
        uint32_t d2[8][2];                    // [t*4 + jl][{rows r, rows r+8}]
        #pragma unroll
        for (int jl = 0; jl < 4; ++jl) {
            const uint32_t v = sm->b2u[cq*16 + jl*4 + (lane & 3)];
            d2[jl][0]   = v; d2[jl][1]   = v;
            d2[4+jl][0] = v; d2[4+jl][1] = v;
        }

        // ---------- fused layer1 + layer2 (f16 accum), per k-step ----------
        #pragma unroll
        for (int s = 0; s < 8; ++s) {
            uint32_t wb0, wb1;
            ldmx2(wb0, wb1, w1AddrBase + (uint32_t)(s * 256));

            uint32_t pk[2][4];
            #pragma unroll
            for (int t = 0; t < 2; ++t) {
                uint32_t u0, u1, u2, u3;
                mma_k8_f16(u0, u1, ai[t][0], ai[t][1], wb0, zero);
                mma_k8_f16(u2, u3, ai[t][0], ai[t][1], wb1, zero);
                pk[t][0] = relu_h2(u0);
                pk[t][1] = relu_h2(u1);
                pk[t][2] = relu_h2(u2);
                pk[t][3] = relu_h2(u3);
            }

            const int c  = 2*s + kSel;
            const int cs = (c & 8) | ((c ^ rowPart) & 7);
            #pragma unroll
            for (int j = 0; j < 2; ++j) {     // n-pair index within col quarter
                uint32_t br0, br1, br2, br3;
                ldmx4(br0, br1, br2, br3,
                      bAddrBase + (uint32_t)(j * 4096) + (uint32_t)cs * 16u);
                mma_k16_f16(d2[2*j][0],     d2[2*j][1],
                            pk[0][0], pk[0][1], pk[0][2], pk[0][3], br0, br1);
                mma_k16_f16(d2[2*j+1][0],   d2[2*j+1][1],
                            pk[0][0], pk[0][1], pk[0][2], pk[0][3], br2, br3);
                mma_k16_f16(d2[4+2*j][0],   d2[4+2*j][1],
                            pk[1][0], pk[1][1], pk[1][2], pk[1][3], br0, br1);
                mma_k16_f16(d2[4+2*j+1][0], d2[4+2*j+1][1],
                            pk[1][0], pk[1][1], pk[1][2], pk[1][3], br2, br3);
            }
        }

        // ---------- layer 3 as MMA (fp32 accum); W3eff frags from smem ----------
        float o3[2][4];
        o3[0][0]=o3[0][1]=o3[0][2]=o3[0][3]=0.f;
        o3[1][0]=o3[1][1]=o3[1][2]=o3[1][3]=0.f;
        {
            const int nn = lane >> 2;
            #pragma unroll
            for (int s3 = 0; s3 < 2; ++s3) {
                uint32_t w3b0 = 0u, w3b1 = 0u;
                if (nn < 4) {
                    const int k0 = cq*32 + s3*16 + (lane & 3)*2;
                    w3b0 = *reinterpret_cast<const uint32_t*>(sm->w3th + nn*128 + k0);
                    w3b1 = *reinterpret_cast<const uint32_t*>(sm->w3th + nn*128 + k0 + 8);
                }
                const int j0 = 2*s3, j1 = 2*s3 + 1;
                #pragma unroll
                for (int t = 0; t < 2; ++t) {
                    const uint32_t a0 = relu_h2(d2[t*4 + j0][0]);
                    const uint32_t a1 = relu_h2(d2[t*4 + j0][1]);
                    const uint32_t a2 = relu_h2(d2[t*4 + j1][0]);
                    const uint32_t a3 = relu_h2(d2[t*4 + j1][1]);
                    mma_k16(o3[t], a0, a1, a2, a3, w3b0, w3b1);
                }
            }
        }

        // ---------- write layer-3 partials ----------
        if ((lane & 3) < 2) {
            #pragma unroll
            for (int t = 0; t < 2; ++t) {
                const int row0 = warpm0 + t*16 + (lane >> 2);
                float2* p0 = reinterpret_cast<float2*>(
                    sm->part[p] + (cq*64 + row0) * 4) + (lane & 3);
                float2* p1 = reinterpret_cast<float2*>(
                    sm->part[p] + (cq*64 + row0 + 8) * 4) + (lane & 3);
                *p0 = make_float2(o3[t][0], o3[t][1]);
                *p1 = make_float2(o3[t][2], o3[t][3]);
            }
        }

        // ---------- invariants for next tile (other buffer) ----------
        if (tid < 64 && ntile < ntiles) compute_inv(sm, p ^ 1, tid, fnx);

        __syncthreads();   // single barrier: covers part[p] and inv/scal[p^1]

        // ---------- final epilogue: combine quarters, rotate, store ----------
        if (tid < 64) {
            const int row  = tid;
            const int elem = tile * 64 + row;
            if (elem < n) {
                const float4 pa = reinterpret_cast<const float4*>(sm->part[p])[row];
                const float4 pb = reinterpret_cast<const float4*>(sm->part[p])[64 + row];
                const float4 pc = reinterpret_cast<const float4*>(sm->part[p])[128 + row];
                const float4 pd = reinterpret_cast<const float4*>(sm->part[p])[192 + row];
                const float x00 = pa.x + pb.x + pc.x + pd.x + sm->b3e[0];
                const float x01 = pa.y + pb.y + pc.y + pd.y + sm->b3e[1];
                const float x11 = pa.z + pb.z + pc.z + pd.z + sm->b3e[2];
                const float4* s = reinterpret_cast<const float4*>(sm->scal[p] + row * 8);
                const float4 fv = s[0];
                const float4 rv = s[1];
                const float r00 = rv.x, r01 = rv.y;
                float4 ov;
                ov.x =  r00*x00 + r01*x01 + fv.x;
                ov.y =  r00*x01 + r01*x11 + fv.y;
                ov.z = -r01*x00 + r00*x01 + fv.z;
                ov.w = -r01*x01 + r00*x11 + fv.w;
                reinterpret_cast<float4*>(out)[elem] = ov;
            }
        }
        p ^= 1;
    }
}

extern "C" void kernel_launch(void* const* d_in, const int* in_sizes, int n_in,
                              void* d_out, int out_size)
{
    const float* F  = (const float*)d_in[0];
    const float* W1 = (const float*)d_in[1];
    const float* b1 = (const float*)d_in[2];
    const float* W2 = (const float*)d_in[3];
    const float* b2 = (const float*)d_in[4];
    const float* W3 = (const float*)d_in[5];
    const float* b3 = (const float*)d_in[6];
    float* out = (float*)d_out;

    const int n = in_sizes[0] / 4;   // number of 2x2 matrices

    const size_t smem_bytes = sizeof(SmemT);
    cudaFuncSetAttribute(defcorr_mma,
                         cudaFuncAttributeMaxDynamicSharedMemorySize, (int)smem_bytes);

    defcorr_mma<<<NBLOCKS, NTHREADS, smem_bytes>>>(F, W1, b1, W2, b2, W3, b3, out, n);
}

// round 13
// speedup vs baseline: 1.0621x; 1.0621x over previous
#include <cuda_runtime.h>
#include <cuda_fp16.h>
#include <cstdint>

#define NTHREADS 256
#define NBLOCKS  444            // 3 CTAs/SM x 148 SMs

// ---------------- PTX helpers ----------------
__device__ __forceinline__ uint32_t smem_u32(const void* p) {
    uint32_t a;
    asm("{ .reg .u64 t; cvta.to.shared.u64 t, %1; cvt.u32.u64 %0, t; }" : "=r"(a) : "l"(p));
    return a;
}
__device__ __forceinline__ void ldmx2(uint32_t& r0, uint32_t& r1, uint32_t addr) {
    asm volatile("ldmatrix.sync.aligned.m8n8.x2.shared.b16 {%0,%1}, [%2];"
                 : "=r"(r0), "=r"(r1) : "r"(addr));
}
__device__ __forceinline__ void ldmx4(uint32_t& r0, uint32_t& r1, uint32_t& r2, uint32_t& r3,
                                      uint32_t addr) {
    asm volatile("ldmatrix.sync.aligned.m8n8.x4.shared.b16 {%0,%1,%2,%3}, [%4];"
                 : "=r"(r0), "=r"(r1), "=r"(r2), "=r"(r3) : "r"(addr));
}
__device__ __forceinline__ void mma_k8_f16(uint32_t& d0, uint32_t& d1,
                                           uint32_t a0, uint32_t a1, uint32_t b0,
                                           uint32_t zero) {
    asm volatile("mma.sync.aligned.m16n8k8.row.col.f16.f16.f16.f16 "
                 "{%0,%1}, {%2,%3}, {%4}, {%5,%5};"
                 : "=r"(d0), "=r"(d1)
                 : "r"(a0), "r"(a1), "r"(b0), "r"(zero));
}
__device__ __forceinline__ void mma_k16_f16(uint32_t& d0, uint32_t& d1,
                                            uint32_t a0, uint32_t a1, uint32_t a2,
                                            uint32_t a3, uint32_t b0, uint32_t b1) {
    asm volatile("mma.sync.aligned.m16n8k16.row.col.f16.f16.f16.f16 "
                 "{%0,%1}, {%2,%3,%4,%5}, {%6,%7}, {%0,%1};"
                 : "+r"(d0), "+r"(d1)
                 : "r"(a0), "r"(a1), "r"(a2), "r"(a3), "r"(b0), "r"(b1));
}
__device__ __forceinline__ void mma_k16(float* d, uint32_t a0, uint32_t a1, uint32_t a2,
                                        uint32_t a3, uint32_t b0, uint32_t b1) {
    asm volatile("mma.sync.aligned.m16n8k16.row.col.f32.f16.f16.f32 "
                 "{%0,%1,%2,%3}, {%4,%5,%6,%7}, {%8,%9}, {%0,%1,%2,%3};"
                 : "+f"(d[0]), "+f"(d[1]), "+f"(d[2]), "+f"(d[3])
                 : "r"(a0), "r"(a1), "r"(a2), "r"(a3), "r"(b0), "r"(b1));
}
__device__ __forceinline__ uint32_t pack_h2(float x, float y) {
    __half2 h = __floats2half2_rn(x, y);          // low half = x
    return *reinterpret_cast<uint32_t*>(&h);
}
__device__ __forceinline__ uint32_t relu_h2(uint32_t u) {
    __half2 h = *reinterpret_cast<__half2*>(&u);
    __half2 z = __floats2half2_rn(0.f, 0.f);
    __half2 r = __hmax2(h, z);
    return *reinterpret_cast<uint32_t*>(&r);
}

// ---------------- shared memory (dynamic, ~45 KB -> 3 CTAs/SM) ----------------
struct SmemT {
    __align__(16) uint8_t  w2t[128 * 256];     // W2^T [n][k] half, swizzled (32 KB)
    __align__(16) __half   w1t[128 * 8];       // W1^T (+b1 in k7)            (2 KB)
    __align__(16) __half   inv[2][64 * 8];     // invariants, double-buffered (2 KB)
    __align__(16) float    scal[2][64 * 8];    // {a,b,c,d,r00,r01}, dbl-buf  (4 KB)
    __align__(16) __half   w3th[4 * 128];      // W3eff^T [nn][k] (3 rows+0)  (1 KB)
    __align__(16) float    part[2][2 * 64 * 4];// layer-3 partials, dbl-buf   (4 KB)
    __align__(16) uint32_t b2u[64];            // b2 packed half2 per n-pair
    float b3e[4];                              // {b3_0, (b3_1+b3_2)/2, b3_3, 0}
};

__device__ __forceinline__ void compute_inv(SmemT* sm, int p, int row, float4 f) {
    const float a = f.x, b = f.y, c = f.z, d = f.w;
    const float t0 = a + d, t1 = b - c, t2 = a - d, t3 = b + c;
    const float pp = sqrtf(t0*t0 + t1*t1);
    const float qq = sqrtf(t2*t2 + t3*t3);
    const float i0 = 0.5f*(pp + qq) - 1.f;
    const float i1 = 0.5f*fabsf(pp - qq) - 1.f;
    const float i2 = a*a + c*c - 1.f;
    const float i3 = a*b + c*d;          // == i4
    const float i5 = b*b + d*d - 1.f;
    const float i6 = a*d - b*c - 1.f;
    const float rp  = 1.f / pp;
    const float r00 = t0 * rp, r01 = t1 * rp;

    uint4 u;
    u.x = pack_h2(i0, i1);
    u.y = pack_h2(i2, i3);
    u.z = pack_h2(i3, i5);
    u.w = pack_h2(i6, 1.0f);             // k7 = 1.0 (bias input)
    reinterpret_cast<uint4*>(sm->inv[p])[row] = u;

    float4* s = reinterpret_cast<float4*>(sm->scal[p] + row * 8);
    s[0] = f;
    s[1] = make_float4(r00, r01, 0.f, 0.f);
}

__global__ __launch_bounds__(NTHREADS, 3)
void defcorr_mma(const float* __restrict__ Fg,
                 const float* __restrict__ W1, const float* __restrict__ b1,
                 const float* __restrict__ W2, const float* __restrict__ b2,
                 const float* __restrict__ W3, const float* __restrict__ b3,
                 float* __restrict__ out, int n)
{
    extern __shared__ char dsm[];
    SmemT* sm = reinterpret_cast<SmemT*>(dsm);

    const int tid  = threadIdx.x;
    const int lane = tid & 31;
    const int warp = tid >> 5;
    const int rg   = warp >> 1;               // row group (0..3): 16 rows each
    const int ch   = warp & 1;                // column half: 64 cols each
    const int warpm0 = rg * 16;

    // ---------- stage weights (once) ----------
    for (int i = tid; i < 128 * 128; i += NTHREADS) {
        const int nn = i >> 7, k = i & 127;
        const int c  = k >> 3;
        const int cs = (c & 8) | ((c ^ nn) & 7);
        const uint32_t off = (uint32_t)nn * 256u + (uint32_t)cs * 16u + (uint32_t)(k & 7) * 2u;
        *reinterpret_cast<__half*>(sm->w2t + off) = __float2half(W2[k * 128 + nn]);
    }
    for (int i = tid; i < 128 * 8; i += NTHREADS) {
        const int nn = i >> 3, k = i & 7;
        sm->w1t[i] = __float2half(k < 7 ? W1[k * 128 + nn] : b1[nn]);
    }
    for (int i = tid; i < 4 * 128; i += NTHREADS) {
        const int nn = i >> 7, k = i & 127;
        float v = 0.f;
        if (nn == 0) v = W3[k * 4 + 0];
        else if (nn == 1) v = 0.5f * (W3[k * 4 + 1] + W3[k * 4 + 2]);   // folded symmetrize
        else if (nn == 2) v = W3[k * 4 + 3];
        sm->w3th[i] = __float2half(v);
    }
    for (int i = tid; i < 64; i += NTHREADS)
        sm->b2u[i] = pack_h2(b2[2*i], b2[2*i + 1]);
    if (tid == 0) {
        sm->b3e[0] = b3[0];
        sm->b3e[1] = 0.5f * (b3[1] + b3[2]);
        sm->b3e[2] = b3[3];
        sm->b3e[3] = 0.f;
    }

    const uint32_t uW2  = smem_u32(sm->w2t);
    const uint32_t uW1  = smem_u32(sm->w1t);
    const uint32_t uInv = smem_u32(sm->inv[0]);

    const int rowPart = ((lane >> 4) << 3) | (lane & 7);
    const int kSel    = (lane >> 3) & 1;
    const uint32_t bAddrBase  = uW2 + (uint32_t)rowPart * 256u + (uint32_t)(ch * 4) * 4096u;
    const uint32_t w1AddrBase = uW1 + (uint32_t)(lane & 15) * 16u;

    __syncthreads();   // weights staged

    const int ntiles = (n + 63) >> 6;         // 64-row tiles

    // ---------- prologue: invariants for first tile into buffer 0 ----------
    if (tid < 64 && blockIdx.x < ntiles) {
        const int elem = blockIdx.x * 64 + tid;
        float4 f = make_float4(1.f, 0.f, 0.f, 1.f);
        if (elem < n) f = reinterpret_cast<const float4*>(Fg)[elem];
        compute_inv(sm, 0, tid, f);
    }
    __syncthreads();

    const uint32_t zero = 0u;
    int p = 0;
    for (int tile = blockIdx.x; tile < ntiles; tile += gridDim.x) {
        const int ntile = tile + gridDim.x;

        // ---------- prefetch next tile's F early (hides LDG behind MMA) ----------
        float4 fnx = make_float4(1.f, 0.f, 0.f, 1.f);
        if (tid < 64 && ntile < ntiles) {
            const int e = ntile * 64 + tid;
            if (e < n) fnx = reinterpret_cast<const float4*>(Fg)[e];
        }

        // ---------- A-inputs for layer 1 (this warp's 16 rows) ----------
        const uint32_t uInvP = uInv + (uint32_t)p * 1024u;
        uint32_t ai0, ai1;
        ldmx2(ai0, ai1, uInvP + (uint32_t)(warpm0 + (lane & 15)) * 16u);

        // ---------- init layer-2 f16 accumulators with b2 ----------
        uint32_t d2[8][2];                    // [n-tile][{rows r, rows r+8}]
        #pragma unroll
        for (int jl = 0; jl < 8; ++jl) {
            const uint32_t v = sm->b2u[ch*32 + jl*4 + (lane & 3)];
            d2[jl][0] = v; d2[jl][1] = v;
        }

        // ---------- fused layer1 + layer2 (f16 accum), per k-step ----------
        #pragma unroll
        for (int s = 0; s < 8; ++s) {
            uint32_t wb0, wb1;
            ldmx2(wb0, wb1, w1AddrBase + (uint32_t)(s * 256));

            uint32_t u0, u1, u2, u3;
            mma_k8_f16(u0, u1, ai0, ai1, wb0, zero);
            mma_k8_f16(u2, u3, ai0, ai1, wb1, zero);
            const uint32_t pk0 = relu_h2(u0);
            const uint32_t pk1 = relu_h2(u1);
            const uint32_t pk2 = relu_h2(u2);
            const uint32_t pk3 = relu_h2(u3);

            const int c  = 2*s + kSel;
            const int cs = (c & 8) | ((c ^ rowPart) & 7);
            #pragma unroll
            for (int j = 0; j < 4; ++j) {     // n-pair index within col half
                uint32_t br0, br1, br2, br3;
                ldmx4(br0, br1, br2, br3,
                      bAddrBase + (uint32_t)(j * 4096) + (uint32_t)cs * 16u);
                mma_k16_f16(d2[2*j][0],   d2[2*j][1],   pk0, pk1, pk2, pk3, br0, br1);
                mma_k16_f16(d2[2*j+1][0], d2[2*j+1][1], pk0, pk1, pk2, pk3, br2, br3);
            }
        }

        // ---------- layer 3 as MMA (fp32 accum); W3eff frags from smem ----------
        float o3[4];
        o3[0] = o3[1] = o3[2] = o3[3] = 0.f;
        {
            const int nn = lane >> 2;
            #pragma unroll
            for (int s3 = 0; s3 < 4; ++s3) {
                uint32_t w3b0 = 0u, w3b1 = 0u;
                if (nn < 4) {
                    const int k0 = ch*64 + s3*16 + (lane & 3)*2;
                    w3b0 = *reinterpret_cast<const uint32_t*>(sm->w3th + nn*128 + k0);
                    w3b1 = *reinterpret_cast<const uint32_t*>(sm->w3th + nn*128 + k0 + 8);
                }
                const int j0 = 2*s3, j1 = 2*s3 + 1;
                const uint32_t a0 = relu_h2(d2[j0][0]);
                const uint32_t a1 = relu_h2(d2[j0][1]);
                const uint32_t a2 = relu_h2(d2[j1][0]);
                const uint32_t a3 = relu_h2(d2[j1][1]);
                mma_k16(o3, a0, a1, a2, a3, w3b0, w3b1);
            }
        }

        // ---------- write layer-3 partials (lanes with n<2 real; n0..2 used) ----------
        if ((lane & 3) < 2) {
            const int row0 = warpm0 + (lane >> 2);
            float2* p0 = reinterpret_cast<float2*>(
                sm->part[p] + (ch*64 + row0) * 4) + (lane & 3);
            float2* p1 = reinterpret_cast<float2*>(
                sm->part[p] + (ch*64 + row0 + 8) * 4) + (lane & 3);
            *p0 = make_float2(o3[0], o3[1]);
            *p1 = make_float2(o3[2], o3[3]);
        }

        // ---------- invariants for next tile (other buffer) ----------
        if (tid < 64 && ntile < ntiles) compute_inv(sm, p ^ 1, tid, fnx);

        __syncthreads();   // single barrier: covers part[p] and inv/scal[p^1]

        // ---------- final epilogue: combine halves, rotate, store ----------
        if (tid < 64) {
            const int row  = tid;
            const int elem = tile * 64 + row;
            if (elem < n) {
                const float4 pa = reinterpret_cast<const float4*>(sm->part[p])[row];
                const float4 pb = reinterpret_cast<const float4*>(sm->part[p])[64 + row];
                const float x00 = pa.x + pb.x + sm->b3e[0];
                const float x01 = pa.y + pb.y + sm->b3e[1];
                const float x11 = pa.z + pb.z + sm->b3e[2];
                const float4* s = reinterpret_cast<const float4*>(sm->scal[p] + row * 8);
                const float4 fv = s[0];
                const float4 rv = s[1];
                const float r00 = rv.x, r01 = rv.y;
                float4 ov;
                ov.x =  r00*x00 + r01*x01 + fv.x;
                ov.y =  r00*x01 + r01*x11 + fv.y;
                ov.z = -r01*x00 + r00*x01 + fv.z;
                ov.w = -r01*x01 + r00*x11 + fv.w;
                reinterpret_cast<float4*>(out)[elem] = ov;
            }
        }
        p ^= 1;
    }
}

extern "C" void kernel_launch(void* const* d_in, const int* in_sizes, int n_in,
                              void* d_out, int out_size)
{
    const float* F  = (const float*)d_in[0];
    const float* W1 = (const float*)d_in[1];
    const float* b1 = (const float*)d_in[2];
    const float* W2 = (const float*)d_in[3];
    const float* b2 = (const float*)d_in[4];
    const float* W3 = (const float*)d_in[5];
    const float* b3 = (const float*)d_in[6];
    float* out = (float*)d_out;

    const int n = in_sizes[0] / 4;   // number of 2x2 matrices

    const size_t smem_bytes = sizeof(SmemT);
    cudaFuncSetAttribute(defcorr_mma,
                         cudaFuncAttributeMaxDynamicSharedMemorySize, (int)smem_bytes);

    defcorr_mma<<<NBLOCKS, NTHREADS, smem_bytes>>>(F, W1, b1, W2, b2, W3, b3, out, n);
}

// round 14
// speedup vs baseline: 1.2411x; 1.1685x over previous
#include <cuda_runtime.h>
#include <cuda_fp16.h>
#include <cstdint>

#define NTHREADS 256
#define NBLOCKS  296

// ---------------- PTX helpers ----------------
__device__ __forceinline__ uint32_t smem_u32(const void* p) {
    uint32_t a;
    asm("{ .reg .u64 t; cvta.to.shared.u64 t, %1; cvt.u32.u64 %0, t; }" : "=r"(a) : "l"(p));
    return a;
}
__device__ __forceinline__ void ldmx2(uint32_t& r0, uint32_t& r1, uint32_t addr) {
    asm volatile("ldmatrix.sync.aligned.m8n8.x2.shared.b16 {%0,%1}, [%2];"
                 : "=r"(r0), "=r"(r1) : "r"(addr));
}
__device__ __forceinline__ void ldmx4(uint32_t& r0, uint32_t& r1, uint32_t& r2, uint32_t& r3,
                                      uint32_t addr) {
    asm volatile("ldmatrix.sync.aligned.m8n8.x4.shared.b16 {%0,%1,%2,%3}, [%4];"
                 : "=r"(r0), "=r"(r1), "=r"(r2), "=r"(r3) : "r"(addr));
}
__device__ __forceinline__ void mma_k8_f16(uint32_t& d0, uint32_t& d1,
                                           uint32_t a0, uint32_t a1, uint32_t b0,
                                           uint32_t zero) {
    asm volatile("mma.sync.aligned.m16n8k8.row.col.f16.f16.f16.f16 "
                 "{%0,%1}, {%2,%3}, {%4}, {%5,%5};"
                 : "=r"(d0), "=r"(d1)
                 : "r"(a0), "r"(a1), "r"(b0), "r"(zero));
}
__device__ __forceinline__ void mma_k16_f16(uint32_t& d0, uint32_t& d1,
                                            uint32_t a0, uint32_t a1, uint32_t a2,
                                            uint32_t a3, uint32_t b0, uint32_t b1) {
    asm volatile("mma.sync.aligned.m16n8k16.row.col.f16.f16.f16.f16 "
                 "{%0,%1}, {%2,%3,%4,%5}, {%6,%7}, {%0,%1};"
                 : "+r"(d0), "+r"(d1)
                 : "r"(a0), "r"(a1), "r"(a2), "r"(a3), "r"(b0), "r"(b1));
}
__device__ __forceinline__ void mma_k16(float* d, uint32_t a0, uint32_t a1, uint32_t a2,
                                        uint32_t a3, uint32_t b0, uint32_t b1) {
    asm volatile("mma.sync.aligned.m16n8k16.row.col.f32.f16.f16.f32 "
                 "{%0,%1,%2,%3}, {%4,%5,%6,%7}, {%8,%9}, {%0,%1,%2,%3};"
                 : "+f"(d[0]), "+f"(d[1]), "+f"(d[2]), "+f"(d[3])
                 : "r"(a0), "r"(a1), "r"(a2), "r"(a3), "r"(b0), "r"(b1));
}
__device__ __forceinline__ uint32_t pack_h2(float x, float y) {
    __half2 h = __floats2half2_rn(x, y);          // low half = x
    return *reinterpret_cast<uint32_t*>(&h);
}
__device__ __forceinline__ uint32_t relu_h2(uint32_t u) {
    __half2 h = *reinterpret_cast<__half2*>(&u);
    __half2 z = __floats2half2_rn(0.f, 0.f);
    __half2 r = __hmax2(h, z);
    return *reinterpret_cast<uint32_t*>(&r);
}

// ---------------- shared memory (dynamic, ~63 KB -> 2 CTAs/SM) ----------------
struct SmemT {
    __align__(16) uint8_t  w2t[128 * 256];     // W2^T [n][k] half, swizzled (32 KB)
    __align__(16) __half   w1t[128 * 8];       // W1^T (+b1 in k7)            (2 KB)
    __align__(16) __half   inv[3][128 * 8];    // invariants, triple-buffered (6 KB)
    __align__(16) float    scal[3][128 * 8];   // {a,b,c,d,r00,r01}, 3-buf   (12 KB)
    __align__(16) __half   w3th[4 * 128];      // W3eff^T [nn][k] (3 rows+0)  (1 KB)
    __align__(16) float    part[2][2 * 128 * 4];// layer-3 partials, dbl-buf  (8 KB)
    __align__(16) uint32_t b2u[64];            // b2 packed half2 per n-pair
    float b3e[4];                              // {b3_0, (b3_1+b3_2)/2, b3_3, 0}
};

__device__ __forceinline__ void compute_inv(SmemT* sm, int q, int row, float4 f) {
    const float a = f.x, b = f.y, c = f.z, d = f.w;
    const float t0 = a + d, t1 = b - c, t2 = a - d, t3 = b + c;
    const float pp = sqrtf(t0*t0 + t1*t1);
    const float qq = sqrtf(t2*t2 + t3*t3);
    const float i0 = 0.5f*(pp + qq) - 1.f;
    const float i1 = 0.5f*fabsf(pp - qq) - 1.f;
    const float i2 = a*a + c*c - 1.f;
    const float i3 = a*b + c*d;          // == i4
    const float i5 = b*b + d*d - 1.f;
    const float i6 = a*d - b*c - 1.f;
    const float rp  = 1.f / pp;
    const float r00 = t0 * rp, r01 = t1 * rp;

    uint4 u;
    u.x = pack_h2(i0, i1);
    u.y = pack_h2(i2, i3);
    u.z = pack_h2(i3, i5);
    u.w = pack_h2(i6, 1.0f);             // k7 = 1.0 (bias input)
    reinterpret_cast<uint4*>(sm->inv[q])[row] = u;

    float4* s = reinterpret_cast<float4*>(sm->scal[q] + row * 8);
    s[0] = f;
    s[1] = make_float4(r00, r01, 0.f, 0.f);
}

__global__ __launch_bounds__(NTHREADS, 2)
void defcorr_mma(const float* __restrict__ Fg,
                 const float* __restrict__ W1, const float* __restrict__ b1,
                 const float* __restrict__ W2, const float* __restrict__ b2,
                 const float* __restrict__ W3, const float* __restrict__ b3,
                 float* __restrict__ out, int n)
{
    extern __shared__ char dsm[];
    SmemT* sm = reinterpret_cast<SmemT*>(dsm);

    const int tid  = threadIdx.x;
    const int lane = tid & 31;
    const int warp = tid >> 5;
    const int rg   = warp >> 1;               // row group: 32 rows each
    const int ch   = warp & 1;                // column half: 64 cols each
    const int warpm0 = rg * 32;

    // ---------- stage weights (once) ----------
    for (int i = tid; i < 128 * 128; i += NTHREADS) {
        const int nn = i >> 7, k = i & 127;
        const int c  = k >> 3;
        const int cs = (c & 8) | ((c ^ nn) & 7);
        const uint32_t off = (uint32_t)nn * 256u + (uint32_t)cs * 16u + (uint32_t)(k & 7) * 2u;
        *reinterpret_cast<__half*>(sm->w2t + off) = __float2half(W2[k * 128 + nn]);
    }
    for (int i = tid; i < 128 * 8; i += NTHREADS) {
        const int nn = i >> 3, k = i & 7;
        sm->w1t[i] = __float2half(k < 7 ? W1[k * 128 + nn] : b1[nn]);
    }
    for (int i = tid; i < 4 * 128; i += NTHREADS) {
        const int nn = i >> 7, k = i & 127;
        float v = 0.f;
        if (nn == 0) v = W3[k * 4 + 0];
        else if (nn == 1) v = 0.5f * (W3[k * 4 + 1] + W3[k * 4 + 2]);   // folded symmetrize
        else if (nn == 2) v = W3[k * 4 + 3];
        sm->w3th[i] = __float2half(v);
    }
    for (int i = tid; i < 64; i += NTHREADS)
        sm->b2u[i] = pack_h2(b2[2*i], b2[2*i + 1]);
    if (tid == 0) {
        sm->b3e[0] = b3[0];
        sm->b3e[1] = 0.5f * (b3[1] + b3[2]);
        sm->b3e[2] = b3[3];
        sm->b3e[3] = 0.f;
    }

    const uint32_t uW2  = smem_u32(sm->w2t);
    const uint32_t uW1  = smem_u32(sm->w1t);
    const uint32_t uInv = smem_u32(sm->inv[0]);

    const int rowPart = ((lane >> 4) << 3) | (lane & 7);
    const int kSel    = (lane >> 3) & 1;
    const uint32_t bAddrBase  = uW2 + (uint32_t)rowPart * 256u + (uint32_t)(ch * 4) * 4096u;
    const uint32_t w1AddrBase = uW1 + (uint32_t)(lane & 15) * 16u;

    __syncthreads();   // weights staged

    // ---------- persistent fragments ----------
    uint32_t w1f[8][2];                        // W1 B-frags, all 8 k-steps (16 regs)
    #pragma unroll
    for (int s = 0; s < 8; ++s)
        ldmx2(w1f[s][0], w1f[s][1], w1AddrBase + (uint32_t)(s * 16) * 16u);

    uint32_t brP[2][4][4];                     // W2 B-frags for k-steps 0,1 (32 regs)
    #pragma unroll
    for (int sp = 0; sp < 2; ++sp) {
        const int c0  = 2*sp + kSel;
        const int cs0 = (c0 & 8) | ((c0 ^ rowPart) & 7);
        #pragma unroll
        for (int j = 0; j < 4; ++j)
            ldmx4(brP[sp][j][0], brP[sp][j][1], brP[sp][j][2], brP[sp][j][3],
                  bAddrBase + (uint32_t)(j * 4096) + (uint32_t)cs0 * 16u);
    }

    const int ntiles = (n + 127) >> 7;

    // ---------- prologue: invariants for first tile into buffer 0 ----------
    if (tid < 128 && blockIdx.x < ntiles) {
        const int elem = blockIdx.x * 128 + tid;
        float4 f = make_float4(1.f, 0.f, 0.f, 1.f);
        if (elem < n) f = reinterpret_cast<const float4*>(Fg)[elem];
        compute_inv(sm, 0, tid, f);
    }
    __syncthreads();

    const uint32_t zero = 0u;
    int q = 0;     // 3-phase inv/scal buffer
    int p = 0;     // 2-phase part buffer
    for (int tile = blockIdx.x; tile < ntiles; tile += gridDim.x) {
        const int ntile = tile + gridDim.x;
        const int qn = (q == 2) ? 0 : q + 1;

        // ---------- prefetch next tile's F (warps 0-3; hides LDG behind MMA) ----------
        float4 fnx = make_float4(1.f, 0.f, 0.f, 1.f);
        if (tid < 128 && ntile < ntiles) {
            const int e = ntile * 128 + tid;
            if (e < n) fnx = reinterpret_cast<const float4*>(Fg)[e];
        }

        // ---------- A-inputs for layer 1 (reads inv[q]) ----------
        const uint32_t uInvQ = uInv + (uint32_t)q * 2048u;
        uint32_t ai[2][2];
        ldmx2(ai[0][0], ai[0][1], uInvQ + (uint32_t)(warpm0      + (lane & 15)) * 16u);
        ldmx2(ai[1][0], ai[1][1], uInvQ + (uint32_t)(warpm0 + 16 + (lane & 15)) * 16u);

        // ---------- init layer-2 f16 accumulators with b2 (packed, from smem) ----------
        uint32_t d2[16][2];
        #pragma unroll
        for (int jl = 0; jl < 8; ++jl) {
            const uint32_t v = sm->b2u[ch*32 + jl*4 + (lane & 3)];
            d2[jl][0]   = v; d2[jl][1]   = v;
            d2[8+jl][0] = v; d2[8+jl][1] = v;
        }

        // ---------- fused layer1 + layer2 (f16 accum), per k-step ----------
        #pragma unroll
        for (int s = 0; s < 8; ++s) {
            uint32_t pk[2][4];
            #pragma unroll
            for (int t = 0; t < 2; ++t) {
                uint32_t u0, u1, u2, u3;
                mma_k8_f16(u0, u1, ai[t][0], ai[t][1], w1f[s][0], zero);
                mma_k8_f16(u2, u3, ai[t][0], ai[t][1], w1f[s][1], zero);
                pk[t][0] = relu_h2(u0);
                pk[t][1] = relu_h2(u1);
                pk[t][2] = relu_h2(u2);
                pk[t][3] = relu_h2(u3);
            }

            const int c  = 2*s + kSel;
            const int cs = (c & 8) | ((c ^ rowPart) & 7);
            #pragma unroll
            for (int j = 0; j < 4; ++j) {
                uint32_t br0, br1, br2, br3;
                if (s < 2) {
                    br0 = brP[s][j][0]; br1 = brP[s][j][1];
                    br2 = brP[s][j][2]; br3 = brP[s][j][3];
                } else {
                    ldmx4(br0, br1, br2, br3,
                          bAddrBase + (uint32_t)(j * 4096) + (uint32_t)cs * 16u);
                }
                mma_k16_f16(d2[2*j][0],     d2[2*j][1],
                            pk[0][0], pk[0][1], pk[0][2], pk[0][3], br0, br1);
                mma_k16_f16(d2[2*j+1][0],   d2[2*j+1][1],
                            pk[0][0], pk[0][1], pk[0][2], pk[0][3], br2, br3);
                mma_k16_f16(d2[8+2*j][0],   d2[8+2*j][1],
                            pk[1][0], pk[1][1], pk[1][2], pk[1][3], br0, br1);
                mma_k16_f16(d2[8+2*j+1][0], d2[8+2*j+1][1],
                            pk[1][0], pk[1][1], pk[1][2], pk[1][3], br2, br3);
            }
        }

        // ---------- layer 3 as MMA (fp32 accum); W3eff frags from smem ----------
        float o3[2][4];
        o3[0][0]=o3[0][1]=o3[0][2]=o3[0][3]=0.f;
        o3[1][0]=o3[1][1]=o3[1][2]=o3[1][3]=0.f;
        {
            const int nn = lane >> 2;
            #pragma unroll
            for (int s3 = 0; s3 < 4; ++s3) {
                uint32_t w3b0 = 0u, w3b1 = 0u;
                if (nn < 4) {
                    const int k0 = ch*64 + s3*16 + (lane & 3)*2;
                    w3b0 = *reinterpret_cast<const uint32_t*>(sm->w3th + nn*128 + k0);
                    w3b1 = *reinterpret_cast<const uint32_t*>(sm->w3th + nn*128 + k0 + 8);
                }
                const int j0 = 2*s3, j1 = 2*s3 + 1;
                #pragma unroll
                for (int t = 0; t < 2; ++t) {
                    const uint32_t a0 = relu_h2(d2[t*8 + j0][0]);
                    const uint32_t a1 = relu_h2(d2[t*8 + j0][1]);
                    const uint32_t a2 = relu_h2(d2[t*8 + j1][0]);
                    const uint32_t a3 = relu_h2(d2[t*8 + j1][1]);
                    mma_k16(o3[t], a0, a1, a2, a3, w3b0, w3b1);
                }
            }
        }

        // ---------- write layer-3 partials (lanes n<4 hold {x00,x01,x11,0}) ----------
        if ((lane & 3) < 2) {
            #pragma unroll
            for (int t = 0; t < 2; ++t) {
                const int row0 = warpm0 + t*16 + (lane >> 2);
                float2* p0 = reinterpret_cast<float2*>(
                    sm->part[p] + (ch*128 + row0) * 4) + (lane & 3);
                float2* p1 = reinterpret_cast<float2*>(
                    sm->part[p] + (ch*128 + row0 + 8) * 4) + (lane & 3);
                *p0 = make_float2(o3[t][0], o3[t][1]);
                *p1 = make_float2(o3[t][2], o3[t][3]);
            }
        }

        // ---------- warps 0-3: invariants for next tile into buffer qn ----------
        if (tid < 128 && ntile < ntiles) compute_inv(sm, qn, tid, fnx);

        __syncthreads();   // covers part[p] and inv/scal[qn]

        // ---------- warps 4-7: epilogue for current tile (concurrent with warps
        //            0-3 starting next tile's MMA) ----------
        if (tid >= 128) {
            const int row  = tid - 128;
            const int elem = tile * 128 + row;
            if (elem < n) {
                const float4 pa = reinterpret_cast<const float4*>(sm->part[p])[row];
                const float4 pb = reinterpret_cast<const float4*>(sm->part[p])[128 + row];
                const float x00 = pa.x + pb.x + sm->b3e[0];
                const float x01 = pa.y + pb.y + sm->b3e[1];
                const float x11 = pa.z + pb.z + sm->b3e[2];
                const float4* s = reinterpret_cast<const float4*>(sm->scal[q] + row * 8);
                const float4 fv = s[0];
                const float4 rv = s[1];
                const float r00 = rv.x, r01 = rv.y;
                float4 ov;
                ov.x =  r00*x00 + r01*x01 + fv.x;
                ov.y =  r00*x01 + r01*x11 + fv.y;
                ov.z = -r01*x00 + r00*x01 + fv.z;
                ov.w = -r01*x01 + r00*x11 + fv.w;
                reinterpret_cast<float4*>(out)[elem] = ov;
            }
        }
        q = qn;
        p ^= 1;
    }
}

extern "C" void kernel_launch(void* const* d_in, const int* in_sizes, int n_in,
                              void* d_out, int out_size)
{
    const float* F  = (const float*)d_in[0];
    const float* W1 = (const float*)d_in[1];
    const float* b1 = (const float*)d_in[2];
    const float* W2 = (const float*)d_in[3];
    const float* b2 = (const float*)d_in[4];
    const float* W3 = (const float*)d_in[5];
    const float* b3 = (const float*)d_in[6];
    float* out = (float*)d_out;

    const int n = in_sizes[0] / 4;   // number of 2x2 matrices

    const size_t smem_bytes = sizeof(SmemT);
    cudaFuncSetAttribute(defcorr_mma,
                         cudaFuncAttributeMaxDynamicSharedMemorySize, (int)smem_bytes);

    defcorr_mma<<<NBLOCKS, NTHREADS, smem_bytes>>>(F, W1, b1, W2, b2, W3, b3, out, n);
}

// round 15
// speedup vs baseline: 1.2842x; 1.0347x over previous
#include <cuda_runtime.h>
#include <cuda_fp16.h>
#include <cstdint>

#define NTHREADS 256
#define NBLOCKS  296

// ---------------- PTX helpers ----------------
__device__ __forceinline__ uint32_t smem_u32(const void* p) {
    uint32_t a;
    asm("{ .reg .u64 t; cvta.to.shared.u64 t, %1; cvt.u32.u64 %0, t; }" : "=r"(a) : "l"(p));
    return a;
}
__device__ __forceinline__ void ldmx2(uint32_t& r0, uint32_t& r1, uint32_t addr) {
    asm volatile("ldmatrix.sync.aligned.m8n8.x2.shared.b16 {%0,%1}, [%2];"
                 : "=r"(r0), "=r"(r1) : "r"(addr));
}
__device__ __forceinline__ void ldmx4(uint32_t& r0, uint32_t& r1, uint32_t& r2, uint32_t& r3,
                                      uint32_t addr) {
    asm volatile("ldmatrix.sync.aligned.m8n8.x4.shared.b16 {%0,%1,%2,%3}, [%4];"
                 : "=r"(r0), "=r"(r1), "=r"(r2), "=r"(r3) : "r"(addr));
}
__device__ __forceinline__ void mma_k8_f16(uint32_t& d0, uint32_t& d1,
                                           uint32_t a0, uint32_t a1, uint32_t b0,
                                           uint32_t zero) {
    asm volatile("mma.sync.aligned.m16n8k8.row.col.f16.f16.f16.f16 "
                 "{%0,%1}, {%2,%3}, {%4}, {%5,%5};"
                 : "=r"(d0), "=r"(d1)
                 : "r"(a0), "r"(a1), "r"(b0), "r"(zero));
}
__device__ __forceinline__ void mma_k16_f16(uint32_t& d0, uint32_t& d1,
                                            uint32_t a0, uint32_t a1, uint32_t a2,
                                            uint32_t a3, uint32_t b0, uint32_t b1) {
    asm volatile("mma.sync.aligned.m16n8k16.row.col.f16.f16.f16.f16 "
                 "{%0,%1}, {%2,%3,%4,%5}, {%6,%7}, {%0,%1};"
                 : "+r"(d0), "+r"(d1)
                 : "r"(a0), "r"(a1), "r"(a2), "r"(a3), "r"(b0), "r"(b1));
}
__device__ __forceinline__ void mma_k16(float* d, uint32_t a0, uint32_t a1, uint32_t a2,
                                        uint32_t a3, uint32_t b0, uint32_t b1) {
    asm volatile("mma.sync.aligned.m16n8k16.row.col.f32.f16.f16.f32 "
                 "{%0,%1,%2,%3}, {%4,%5,%6,%7}, {%8,%9}, {%0,%1,%2,%3};"
                 : "+f"(d[0]), "+f"(d[1]), "+f"(d[2]), "+f"(d[3])
                 : "r"(a0), "r"(a1), "r"(a2), "r"(a3), "r"(b0), "r"(b1));
}
__device__ __forceinline__ uint32_t pack_h2(float x, float y) {
    __half2 h = __floats2half2_rn(x, y);          // low half = x
    return *reinterpret_cast<uint32_t*>(&h);
}
__device__ __forceinline__ uint32_t relu_h2(uint32_t u) {
    __half2 h = *reinterpret_cast<__half2*>(&u);
    __half2 z = __floats2half2_rn(0.f, 0.f);
    __half2 r = __hmax2(h, z);
    return *reinterpret_cast<uint32_t*>(&r);
}

// ---------------- shared memory (dynamic, ~76 KB -> 2 CTAs/SM) ----------------
// CTA iteration = 256-element supertile (2 x 128-row subtiles); B frags reused
// across 4 m-tiles per warp -> per-element LDSM traffic halves vs M32xN64/128.
struct SmemT {
    __align__(16) uint8_t  w2t[128 * 256];      // W2^T [n][k] half, swizzled (32 KB)
    __align__(16) __half   w1t[128 * 8];        // W1^T (+b1 in k7)            (2 KB)
    __align__(16) __half   inv[2][256 * 8];     // invariants, double-buffered (8 KB)
    __align__(16) float    scal[2][256 * 8];    // {a,b,c,d,r00,r01}, dbl-buf (16 KB)
    __align__(16) __half   w3th[4 * 128];       // W3eff^T [nn][k] (3 rows+0)  (1 KB)
    __align__(16) float    part[2][2 * 256 * 4];// layer-3 partials, dbl-buf  (16 KB)
    __align__(16) uint32_t b2u[64];             // b2 packed half2 per n-pair
    float b3e[4];                               // {b3_0, (b3_1+b3_2)/2, b3_3, 0}
};

__device__ __forceinline__ void compute_inv(SmemT* sm, int q, int row, float4 f) {
    const float a = f.x, b = f.y, c = f.z, d = f.w;
    const float t0 = a + d, t1 = b - c, t2 = a - d, t3 = b + c;
    const float pp = sqrtf(t0*t0 + t1*t1);
    const float qq = sqrtf(t2*t2 + t3*t3);
    const float i0 = 0.5f*(pp + qq) - 1.f;
    const float i1 = 0.5f*fabsf(pp - qq) - 1.f;
    const float i2 = a*a + c*c - 1.f;
    const float i3 = a*b + c*d;          // == i4
    const float i5 = b*b + d*d - 1.f;
    const float i6 = a*d - b*c - 1.f;
    const float rp  = 1.f / pp;
    const float r00 = t0 * rp, r01 = t1 * rp;

    uint4 u;
    u.x = pack_h2(i0, i1);
    u.y = pack_h2(i2, i3);
    u.z = pack_h2(i3, i5);
    u.w = pack_h2(i6, 1.0f);             // k7 = 1.0 (bias input)
    reinterpret_cast<uint4*>(sm->inv[q])[row] = u;

    float4* s = reinterpret_cast<float4*>(sm->scal[q] + row * 8);
    s[0] = f;
    s[1] = make_float4(r00, r01, 0.f, 0.f);
}

__global__ __launch_bounds__(NTHREADS, 2)
void defcorr_mma(const float* __restrict__ Fg,
                 const float* __restrict__ W1, const float* __restrict__ b1,
                 const float* __restrict__ W2, const float* __restrict__ b2,
                 const float* __restrict__ W3, const float* __restrict__ b3,
                 float* __restrict__ out, int n)
{
    extern __shared__ char dsm[];
    SmemT* sm = reinterpret_cast<SmemT*>(dsm);

    const int tid  = threadIdx.x;
    const int lane = tid & 31;
    const int warp = tid >> 5;
    const int rg   = warp >> 1;               // row group (0..3): 32 rows per subtile
    const int ch   = warp & 1;                // column half: 64 cols each
    const int warpm0 = rg * 32;

    // ---------- stage weights (once) ----------
    for (int i = tid; i < 128 * 128; i += NTHREADS) {
        const int nn = i >> 7, k = i & 127;
        const int c  = k >> 3;
        const int cs = (c & 8) | ((c ^ nn) & 7);
        const uint32_t off = (uint32_t)nn * 256u + (uint32_t)cs * 16u + (uint32_t)(k & 7) * 2u;
        *reinterpret_cast<__half*>(sm->w2t + off) = __float2half(W2[k * 128 + nn]);
    }
    for (int i = tid; i < 128 * 8; i += NTHREADS) {
        const int nn = i >> 3, k = i & 7;
        sm->w1t[i] = __float2half(k < 7 ? W1[k * 128 + nn] : b1[nn]);
    }
    for (int i = tid; i < 4 * 128; i += NTHREADS) {
        const int nn = i >> 7, k = i & 127;
        float v = 0.f;
        if (nn == 0) v = W3[k * 4 + 0];
        else if (nn == 1) v = 0.5f * (W3[k * 4 + 1] + W3[k * 4 + 2]);   // folded symmetrize
        else if (nn == 2) v = W3[k * 4 + 3];
        sm->w3th[i] = __float2half(v);
    }
    for (int i = tid; i < 64; i += NTHREADS)
        sm->b2u[i] = pack_h2(b2[2*i], b2[2*i + 1]);
    if (tid == 0) {
        sm->b3e[0] = b3[0];
        sm->b3e[1] = 0.5f * (b3[1] + b3[2]);
        sm->b3e[2] = b3[3];
        sm->b3e[3] = 0.f;
    }

    const uint32_t uW2  = smem_u32(sm->w2t);
    const uint32_t uW1  = smem_u32(sm->w1t);
    const uint32_t uInv = smem_u32(sm->inv[0]);

    const int rowPart = ((lane >> 4) << 3) | (lane & 7);
    const int kSel    = (lane >> 3) & 1;
    const uint32_t bAddrBase  = uW2 + (uint32_t)rowPart * 256u + (uint32_t)(ch * 4) * 4096u;
    const uint32_t w1AddrBase = uW1 + (uint32_t)(lane & 15) * 16u;

    __syncthreads();   // weights staged

    const int ntiles = (n + 255) >> 8;        // 256-element supertiles

    // ---------- prologue: invariants for first supertile into buffer 0 ----------
    if (blockIdx.x < ntiles) {
        const int elem = blockIdx.x * 256 + tid;
        float4 f = make_float4(1.f, 0.f, 0.f, 1.f);
        if (elem < n) f = reinterpret_cast<const float4*>(Fg)[elem];
        compute_inv(sm, 0, tid, f);
    }
    __syncthreads();

    const uint32_t zero = 0u;
    int q = 0;     // inv/scal buffer
    int p = 0;     // part buffer
    for (int tile = blockIdx.x; tile < ntiles; tile += gridDim.x) {
        const int ntile = tile + gridDim.x;

        // ---------- prefetch next supertile's F (hides LDG behind MMA) ----------
        float4 fnx = make_float4(1.f, 0.f, 0.f, 1.f);
        if (ntile < ntiles) {
            const int e = ntile * 256 + tid;
            if (e < n) fnx = reinterpret_cast<const float4*>(Fg)[e];
        }

        // ---------- A-inputs: 4 m-tiles = {subtile 0, subtile 1} x {lo16, hi16} ----------
        const uint32_t uInvQ = uInv + (uint32_t)q * 4096u;
        uint32_t ai[4][2];
        #pragma unroll
        for (int m = 0; m < 4; ++m) {
            const int grow = (m >> 1) * 128 + warpm0 + (m & 1) * 16 + (lane & 15);
            ldmx2(ai[m][0], ai[m][1], uInvQ + (uint32_t)grow * 16u);
        }

        // ---------- init layer-2 f16 accumulators with b2 ----------
        uint32_t d2[32][2];                   // [m*8 + jl]
        #pragma unroll
        for (int jl = 0; jl < 8; ++jl) {
            const uint32_t v = sm->b2u[ch*32 + jl*4 + (lane & 3)];
            #pragma unroll
            for (int m = 0; m < 4; ++m) { d2[m*8 + jl][0] = v; d2[m*8 + jl][1] = v; }
        }

        // ---------- fused layer1 + layer2 (f16 accum), per k-step ----------
        #pragma unroll
        for (int s = 0; s < 8; ++s) {
            uint32_t wb0, wb1;
            ldmx2(wb0, wb1, w1AddrBase + (uint32_t)(s * 256));

            uint32_t pk[4][4];
            #pragma unroll
            for (int m = 0; m < 4; ++m) {
                uint32_t u0, u1, u2, u3;
                mma_k8_f16(u0, u1, ai[m][0], ai[m][1], wb0, zero);
                mma_k8_f16(u2, u3, ai[m][0], ai[m][1], wb1, zero);
                pk[m][0] = relu_h2(u0);
                pk[m][1] = relu_h2(u1);
                pk[m][2] = relu_h2(u2);
                pk[m][3] = relu_h2(u3);
            }

            const int c  = 2*s + kSel;
            const int cs = (c & 8) | ((c ^ rowPart) & 7);
            #pragma unroll
            for (int j = 0; j < 4; ++j) {     // n-pair within col half; B reused 4x
                uint32_t br0, br1, br2, br3;
                ldmx4(br0, br1, br2, br3,
                      bAddrBase + (uint32_t)(j * 4096) + (uint32_t)cs * 16u);
                #pragma unroll
                for (int m = 0; m < 4; ++m) {
                    mma_k16_f16(d2[m*8 + 2*j][0],   d2[m*8 + 2*j][1],
                                pk[m][0], pk[m][1], pk[m][2], pk[m][3], br0, br1);
                    mma_k16_f16(d2[m*8 + 2*j+1][0], d2[m*8 + 2*j+1][1],
                                pk[m][0], pk[m][1], pk[m][2], pk[m][3], br2, br3);
                }
            }
        }

        // ---------- layer 3 as MMA (fp32 accum); W3eff frags from smem ----------
        float o3[4][4];
        #pragma unroll
        for (int m = 0; m < 4; ++m) { o3[m][0]=o3[m][1]=o3[m][2]=o3[m][3]=0.f; }
        {
            const int nn = lane >> 2;
            #pragma unroll
            for (int s3 = 0; s3 < 4; ++s3) {
                uint32_t w3b0 = 0u, w3b1 = 0u;
                if (nn < 4) {
                    const int k0 = ch*64 + s3*16 + (lane & 3)*2;
                    w3b0 = *reinterpret_cast<const uint32_t*>(sm->w3th + nn*128 + k0);
                    w3b1 = *reinterpret_cast<const uint32_t*>(sm->w3th + nn*128 + k0 + 8);
                }
                const int j0 = 2*s3, j1 = 2*s3 + 1;
                #pragma unroll
                for (int m = 0; m < 4; ++m) {
                    const uint32_t a0 = relu_h2(d2[m*8 + j0][0]);
                    const uint32_t a1 = relu_h2(d2[m*8 + j0][1]);
                    const uint32_t a2 = relu_h2(d2[m*8 + j1][0]);
                    const uint32_t a3 = relu_h2(d2[m*8 + j1][1]);
                    mma_k16(o3[m], a0, a1, a2, a3, w3b0, w3b1);
                }
            }
        }

        // ---------- write layer-3 partials ----------
        if ((lane & 3) < 2) {
            #pragma unroll
            for (int m = 0; m < 4; ++m) {
                const int grow = (m >> 1) * 128 + warpm0 + (m & 1) * 16 + (lane >> 2);
                float2* p0 = reinterpret_cast<float2*>(
                    sm->part[p] + (ch*256 + grow) * 4) + (lane & 3);
                float2* p1 = reinterpret_cast<float2*>(
                    sm->part[p] + (ch*256 + grow + 8) * 4) + (lane & 3);
                *p0 = make_float2(o3[m][0], o3[m][1]);
                *p1 = make_float2(o3[m][2], o3[m][3]);
            }
        }

        // ---------- invariants for next supertile (other buffer; own row) ----------
        if (ntile < ntiles) compute_inv(sm, q ^ 1, tid, fnx);

        __syncthreads();   // single barrier: covers part[p] and inv/scal[q^1]

        // ---------- epilogue: all 256 threads, one row each ----------
        {
            const int row  = tid;
            const int elem = tile * 256 + row;
            if (elem < n) {
                const float4 pa = reinterpret_cast<const float4*>(sm->part[p])[row];
                const float4 pb = reinterpret_cast<const float4*>(sm->part[p])[256 + row];
                const float x00 = pa.x + pb.x + sm->b3e[0];
                const float x01 = pa.y + pb.y + sm->b3e[1];
                const float x11 = pa.z + pb.z + sm->b3e[2];
                const float4* s = reinterpret_cast<const float4*>(sm->scal[q] + row * 8);
                const float4 fv = s[0];
                const float4 rv = s[1];
                const float r00 = rv.x, r01 = rv.y;
                float4 ov;
                ov.x =  r00*x00 + r01*x01 + fv.x;
                ov.y =  r00*x01 + r01*x11 + fv.y;
                ov.z = -r01*x00 + r00*x01 + fv.z;
                ov.w = -r01*x01 + r00*x11 + fv.w;
                reinterpret_cast<float4*>(out)[elem] = ov;
            }
        }
        q ^= 1;
        p ^= 1;
    }
}

extern "C" void kernel_launch(void* const* d_in, const int* in_sizes, int n_in,
                              void* d_out, int out_size)
{
    const float* F  = (const float*)d_in[0];
    const float* W1 = (const float*)d_in[1];
    const float* b1 = (const float*)d_in[2];
    const float* W2 = (const float*)d_in[3];
    const float* b2 = (const float*)d_in[4];
    const float* W3 = (const float*)d_in[5];
    const float* b3 = (const float*)d_in[6];
    float* out = (float*)d_out;

    const int n = in_sizes[0] / 4;   // number of 2x2 matrices

    const size_t smem_bytes = sizeof(SmemT);
    cudaFuncSetAttribute(defcorr_mma,
                         cudaFuncAttributeMaxDynamicSharedMemorySize, (int)smem_bytes);

    defcorr_mma<<<NBLOCKS, NTHREADS, smem_bytes>>>(F, W1, b1, W2, b2, W3, b3, out, n);
}